// round 6
// baseline (speedup 1.0000x reference)
#include <cuda_runtime.h>
#include <cstdint>

#define BB 64
#define CC 64
#define HH 128
#define WW 128
#define NSLAB (BB * CC)
#define GRID1 148           // persistent, 1 CTA/SM, single wave

// smem layout (floats): buf0[16384] buf1[16384] se[32*128] sy[32*128] smax[32]
#define SMEM1_FLOATS (2 * 16384 + 2 * 4096 + 32)
#define SMEM1_BYTES  (SMEM1_FLOATS * 4)

// Scratch (allocation-free rule: __device__ globals)
__device__ float g_cs_e [NSLAB * WW];   // colsum_e [b,c,w]  = sum_h exp(x-m)
__device__ float g_cs_ey[NSLAB * WW];   // colsum_ey[b,c,w]  = sum_h exp(x-m)*wy[h]

__device__ __forceinline__ void cp16(uint32_t saddr, const void* gaddr) {
    asm volatile("cp.async.cg.shared.global [%0], [%1], 16;\n"
                 :: "r"(saddr), "l"(gaddr));
}
__device__ __forceinline__ void cp_commit() {
    asm volatile("cp.async.commit_group;\n" ::);
}
__device__ __forceinline__ void cp_wait1() {
    asm volatile("cp.async.wait_group 1;\n" :: );
}

// ---------------------------------------------------------------------------
// Pass 1 (persistent, cp.async double-buffered):
//   grid=148, 1024 threads. Each CTA loops over ~28 slabs (128x128 f32=64KB).
//   Loads for slab i+1 are in flight (LDGSTS -> smem) during all of slab i's
//   compute, so DRAM never drains on the max->exp dependency.
//   warp w owns rows 4w..4w+3; lane l owns cols 4l..4l+3.
// ---------------------------------------------------------------------------
__global__ __launch_bounds__(1024, 1)
void sam_pass1(const float* __restrict__ x) {
    extern __shared__ float dsm[];
    float* se   = dsm + 32768;          // [32][128]
    float* sy   = se  + 4096;           // [32][128]
    float* smax = sy  + 4096;           // [32]

    const int tid = threadIdx.x;
    const int w   = tid >> 5;           // warp 0..31
    const int l   = tid & 31;           // lane
    const float inv127 = 1.0f / 127.0f;

    const uint32_t sbase = (uint32_t)__cvta_generic_to_shared(dsm);
    const float4* __restrict__ xg = reinterpret_cast<const float4*>(x);

    int bc = blockIdx.x;
    if (bc < NSLAB) {
        const float4* g = xg + (size_t)bc * 4096;
#pragma unroll
        for (int j = 0; j < 4; j++)
            cp16(sbase + (uint32_t)(tid + 1024 * j) * 16, g + tid + 1024 * j);
    }
    cp_commit();

    int cur = 0;
    for (; bc < NSLAB; bc += GRID1, cur ^= 1) {
        // issue next slab into the other buffer (in flight through compute)
        const int nbc = bc + GRID1;
        if (nbc < NSLAB) {
            const float4* g = xg + (size_t)nbc * 4096;
            const uint32_t sb = sbase + (uint32_t)(cur ^ 1) * 65536u;
#pragma unroll
            for (int j = 0; j < 4; j++)
                cp16(sb + (uint32_t)(tid + 1024 * j) * 16, g + tid + 1024 * j);
        }
        cp_commit();
        cp_wait1();                      // current buffer complete (per-thread)
        __syncthreads();                 // A: all threads' copies visible

        // stage this thread's 16 values from smem
        const float4* B = reinterpret_cast<const float4*>(dsm + cur * 16384);
        float4 v[4];
#pragma unroll
        for (int r = 0; r < 4; r++)
            v[r] = B[(4 * w + r) * 32 + l];

        // exact CTA max
        float m = v[0].x;
#pragma unroll
        for (int r = 0; r < 4; r++)
            m = fmaxf(m, fmaxf(fmaxf(v[r].x, v[r].y), fmaxf(v[r].z, v[r].w)));
#pragma unroll
        for (int o = 16; o; o >>= 1)
            m = fmaxf(m, __shfl_xor_sync(0xffffffffu, m, o));
        if (l == 0) smax[w] = m;
        __syncthreads();                 // B
        float mc = smax[0];
#pragma unroll
        for (int k = 1; k < 32; k++) mc = fmaxf(mc, smax[k]);

        // exp + column partial sums (4 rows x 4 cols per thread)
        float ae0 = 0.f, ae1 = 0.f, ae2 = 0.f, ae3 = 0.f;
        float ay0 = 0.f, ay1 = 0.f, ay2 = 0.f, ay3 = 0.f;
#pragma unroll
        for (int r = 0; r < 4; r++) {
            const float wy = (float)(4 * w + r) * inv127;
            float e0 = __expf(v[r].x - mc);
            float e1 = __expf(v[r].y - mc);
            float e2 = __expf(v[r].z - mc);
            float e3 = __expf(v[r].w - mc);
            ae0 += e0; ay0 += e0 * wy;
            ae1 += e1; ay1 += e1 * wy;
            ae2 += e2; ay2 += e2 * wy;
            ae3 += e3; ay3 += e3 * wy;
        }
        reinterpret_cast<float4*>(se)[w * 32 + l] = make_float4(ae0, ae1, ae2, ae3);
        reinterpret_cast<float4*>(sy)[w * 32 + l] = make_float4(ay0, ay1, ay2, ay3);
        __syncthreads();                 // C

        // deterministic combine over 32 warps, write colsums
        if (tid < 128) {
            float s = 0.f;
#pragma unroll
            for (int k = 0; k < 32; k++) s += se[k * 128 + tid];
            g_cs_e[(size_t)bc * WW + tid] = s;
        } else if (tid < 256) {
            const int c = tid - 128;
            float s = 0.f;
#pragma unroll
            for (int k = 0; k < 32; k++) s += sy[k * 128 + c];
            g_cs_ey[(size_t)bc * WW + c] = s;
        }
    }
}

// ---------------------------------------------------------------------------
// Pass 2: grid = 64 batches x 8 channel-groups = 512 CTAs, 256 threads.
//   Each CTA redundantly computes rs[b,w] (L2-hot) and finishes 8 channels.
//   All global loads are issued before the first barrier.
// ---------------------------------------------------------------------------
__global__ __launch_bounds__(256)
void sam_pass2(float* __restrict__ out) {
    const int b   = blockIdx.x >> 3;
    const int cg  = blockIdx.x & 7;
    const int tid = threadIdx.x;

    const float* __restrict__ cse = g_cs_e  + (size_t)b * CC * WW;
    const float* __restrict__ csy = g_cs_ey + (size_t)b * CC * WW;

    // rs loads: thread (ch, w) sums channels ch*32..ch*32+31 at column w
    const int w2 = tid & 127;
    const int ch = tid >> 7;             // 0..1
    float a[32];
#pragma unroll
    for (int k = 0; k < 32; k++)
        a[k] = cse[(ch * 32 + k) * WW + w2];

    // channel loads: warp wp -> channel cg*8+wp; lane covers 4 columns
    const int wp   = tid >> 5;           // 0..7
    const int lane = tid & 31;
    const int c    = cg * 8 + wp;
    float pe[4], py[4];
#pragma unroll
    for (int j = 0; j < 4; j++) {
        pe[j] = cse[c * WW + lane + 32 * j];
        py[j] = csy[c * WW + lane + 32 * j];
    }

    __shared__ float sA[2][WW];
    __shared__ float rs[WW];
    {
        float s = 0.f;
#pragma unroll
        for (int k = 0; k < 32; k++) s += a[k];
        sA[ch][w2] = s;
    }
    __syncthreads();
    if (tid < WW) rs[tid] = 1.0f / (sA[0][tid] + sA[1][tid]);
    __syncthreads();

    const float inv127 = 1.0f / 127.0f;
    float xx = 0.f, xy = 0.f;
#pragma unroll
    for (int j = 0; j < 4; j++) {
        const int ww = lane + 32 * j;
        const float r = rs[ww];
        xx += pe[j] * ((float)ww * inv127) * r;
        xy += py[j] * r;
    }
#pragma unroll
    for (int o = 16; o; o >>= 1) {
        xx += __shfl_xor_sync(0xffffffffu, xx, o);
        xy += __shfl_xor_sync(0xffffffffu, xy, o);
    }
    if (lane == 0) {
        out[((size_t)b * CC + c) * 2 + 0] = xx;
        out[((size_t)b * CC + c) * 2 + 1] = xy;
    }
}

extern "C" void kernel_launch(void* const* d_in, const int* in_sizes, int n_in,
                              void* d_out, int out_size) {
    const float* x = (const float*)d_in[0];
    float* out = (float*)d_out;
    cudaFuncSetAttribute(sam_pass1, cudaFuncAttributeMaxDynamicSharedMemorySize,
                         SMEM1_BYTES);
    sam_pass1<<<GRID1, 1024, SMEM1_BYTES>>>(x);
    sam_pass2<<<8 * BB, 256>>>(out);
}

// round 7
// speedup vs baseline: 1.1128x; 1.1128x over previous
#include <cuda_runtime.h>
#include <cstdint>

#define BB 64
#define CC 64
#define HH 128
#define WW 128
#define NSLAB (BB * CC)
#define GRID1 296   // persistent, 2 CTAs/SM, single wave

// Scratch (allocation-free rule: __device__ globals)
__device__ float g_cs_e [NSLAB * WW];   // colsum_e [b,c,w]  = sum_h exp(x-m)
__device__ float g_cs_ey[NSLAB * WW];   // colsum_ey[b,c,w]  = sum_h exp(x-m)*wy[h]

__device__ __forceinline__ void l2_prefetch_64k(const void* p) {
    asm volatile("cp.async.bulk.prefetch.L2.global [%0], %1;"
                 :: "l"(p), "r"(65536));
}

// ---------------------------------------------------------------------------
// Pass 1 (persistent): grid-stride over 4096 (b,c) slabs, 512 threads/CTA,
// 2 CTAs/SM, register-staged (16 warps x 32 lanes, 8 float4/thread).
//   - tid 0 issues an L2 bulk prefetch of slab i+2 at loop top: the DRAM
//     stream is driven by consumer-less prefetches (never stalls), and the
//     register loads for slab i+1 (issued mid-iteration) then hit L2 (~250cy)
//     instead of DRAM (~600-1000cy), shrinking the exposed stall at the max.
// ---------------------------------------------------------------------------
__global__ __launch_bounds__(512, 2)
void sam_pass1(const float* __restrict__ x) {
    const int tid = threadIdx.x;
    const int wg  = tid & 31;                   // w-group (4 consecutive floats)
    const int hs  = tid >> 5;                   // warp id == h subgroup 0..15

    __shared__ float  smax[16];
    __shared__ float4 se[16][32];               // [warp][wg] -> flat [16][128]
    __shared__ float4 sy[16][32];

    const float4* __restrict__ xp = reinterpret_cast<const float4*>(x);
    const float inv127 = 1.0f / 127.0f;

    int bc = blockIdx.x;
    float4 v[8];
    if (bc < NSLAB) {
        if (tid == 0 && bc + GRID1 < NSLAB)
            l2_prefetch_64k(xp + (size_t)(bc + GRID1) * (HH * WW / 4));
        const float4* p = xp + (size_t)bc * (HH * WW / 4);
#pragma unroll
        for (int r = 0; r < 8; r++)
            v[r] = p[(hs + 16 * r) * (WW / 4) + wg];
    }

    for (; bc < NSLAB; bc += GRID1) {
        // prefetch slab i+2 into L2 (~1.5 slab-times of lead)
        if (tid == 0 && bc + 2 * GRID1 < NSLAB)
            l2_prefetch_64k(xp + (size_t)(bc + 2 * GRID1) * (HH * WW / 4));

        // ---- warp max, then CTA max ----
        float m = v[0].x;
#pragma unroll
        for (int r = 0; r < 8; r++)
            m = fmaxf(m, fmaxf(fmaxf(v[r].x, v[r].y), fmaxf(v[r].z, v[r].w)));
#pragma unroll
        for (int o = 16; o; o >>= 1)
            m = fmaxf(m, __shfl_xor_sync(0xffffffffu, m, o));
        if (wg == 0) smax[hs] = m;
        __syncthreads();                        // A (also fences se/sy reuse)
        float mc = smax[0];
#pragma unroll
        for (int k = 1; k < 16; k++) mc = fmaxf(mc, smax[k]);

        // ---- exp + per-thread column partial sums (consumes v) ----
        float ae0 = 0.f, ae1 = 0.f, ae2 = 0.f, ae3 = 0.f;
        float ay0 = 0.f, ay1 = 0.f, ay2 = 0.f, ay3 = 0.f;
#pragma unroll
        for (int r = 0; r < 8; r++) {
            const float wy = (float)(hs + 16 * r) * inv127;
            float e0 = __expf(v[r].x - mc);
            float e1 = __expf(v[r].y - mc);
            float e2 = __expf(v[r].z - mc);
            float e3 = __expf(v[r].w - mc);
            ae0 += e0; ay0 += e0 * wy;
            ae1 += e1; ay1 += e1 * wy;
            ae2 += e2; ay2 += e2 * wy;
            ae3 += e3; ay3 += e3 * wy;
        }

        // ---- load next slab (L2-hot thanks to prefetch), overlaps epilogue ----
        const int nbc = bc + GRID1;
        if (nbc < NSLAB) {
            const float4* p = xp + (size_t)nbc * (HH * WW / 4);
#pragma unroll
            for (int r = 0; r < 8; r++)
                v[r] = p[(hs + 16 * r) * (WW / 4) + wg];
        }

        // ---- deterministic combine over 16 warps ----
        se[hs][wg] = make_float4(ae0, ae1, ae2, ae3);
        sy[hs][wg] = make_float4(ay0, ay1, ay2, ay3);
        __syncthreads();                        // B

        if (tid < 128) {
            const float* p = reinterpret_cast<const float*>(se);
            float s = 0.f;
#pragma unroll
            for (int k = 0; k < 16; k++) s += p[k * 128 + tid];
            g_cs_e[(size_t)bc * WW + tid] = s;
        } else if (tid < 256) {
            const int w = tid - 128;
            const float* p = reinterpret_cast<const float*>(sy);
            float s = 0.f;
#pragma unroll
            for (int k = 0; k < 16; k++) s += p[k * 128 + w];
            g_cs_ey[(size_t)bc * WW + w] = s;
        }
    }
}

// ---------------------------------------------------------------------------
// Pass 2: 2 CTAs per batch (grid=128), 512 threads. Each CTA redundantly
// computes rs[b,w] = 1 / sum_c colsum_e (L2-hot), then handles 32 channels.
// All global loads are issued before the first barrier.
// ---------------------------------------------------------------------------
__global__ __launch_bounds__(512)
void sam_pass2(float* __restrict__ out) {
    const int b    = blockIdx.x >> 1;
    const int half = blockIdx.x & 1;
    const int tid  = threadIdx.x;

    const float* __restrict__ cse = g_cs_e  + (size_t)b * CC * WW;
    const float* __restrict__ csy = g_cs_ey + (size_t)b * CC * WW;

    __shared__ float sA[4][WW];
    __shared__ float rs[WW];

    // Loads for rs (sum over all 64 channels, 4 c-groups x 16)
    const int w  = tid & 127;
    const int cg = tid >> 7;                    // 0..3
    float a[16];
#pragma unroll
    for (int k = 0; k < 16; k++)
        a[k] = cse[(cg + 4 * k) * WW + w];

    // Prefetch phase-B channel data (this CTA's 32 channels)
    const int warp = tid >> 5;                  // 0..15
    const int lane = tid & 31;
    float pe[2][4], py[2][4];
#pragma unroll
    for (int i = 0; i < 2; i++) {
        const int c = half * 32 + warp * 2 + i;
#pragma unroll
        for (int j = 0; j < 4; j++) {
            const int ww = lane + 32 * j;
            pe[i][j] = cse[c * WW + ww];
            py[i][j] = csy[c * WW + ww];
        }
    }

    // rs reduce
    {
        float s = 0.f;
#pragma unroll
        for (int k = 0; k < 16; k++) s += a[k];
        sA[cg][w] = s;
    }
    __syncthreads();
    if (tid < WW) {
        rs[tid] = 1.0f / (sA[0][tid] + sA[1][tid] + sA[2][tid] + sA[3][tid]);
    }
    __syncthreads();

    // Phase B: per-channel dot products (data already in registers)
    const float inv127 = 1.0f / 127.0f;
#pragma unroll
    for (int i = 0; i < 2; i++) {
        const int c = half * 32 + warp * 2 + i;
        float xx = 0.f, xy = 0.f;
#pragma unroll
        for (int j = 0; j < 4; j++) {
            const int ww = lane + 32 * j;
            const float r = rs[ww];
            xx += pe[i][j] * ((float)ww * inv127) * r;
            xy += py[i][j] * r;
        }
#pragma unroll
        for (int o = 16; o; o >>= 1) {
            xx += __shfl_xor_sync(0xffffffffu, xx, o);
            xy += __shfl_xor_sync(0xffffffffu, xy, o);
        }
        if (lane == 0) {
            out[((size_t)b * CC + c) * 2 + 0] = xx;
            out[((size_t)b * CC + c) * 2 + 1] = xy;
        }
    }
}

extern "C" void kernel_launch(void* const* d_in, const int* in_sizes, int n_in,
                              void* d_out, int out_size) {
    const float* x = (const float*)d_in[0];
    float* out = (float*)d_out;
    sam_pass1<<<GRID1, 512>>>(x);
    sam_pass2<<<2 * BB, 512>>>(out);
}